// round 8
// baseline (speedup 1.0000x reference)
#include <cuda_runtime.h>
#include <cuda_fp16.h>

#define NN 100000
#define NE 1000000
#define D  64
#define NB 98   // ceil(NN/1024)

typedef unsigned long long ull;

// ---- device scratch (static, no allocation) ----
__device__ int     g_deg[NN];        // edge-count (self loop added in math)
__device__ float   g_dinv[NN];
__device__ int     g_off[NN + 1];
__device__ int     g_bsum[NB];
__device__ int     g_ppos[NE];       // per-edge rank within its dst bucket
__device__ int     g_csr_src[NE];
__device__ __half  g_u0[NN * D];     // fp16 intermediates
__device__ __half  g_u1[NN * D];

// 1) histogram of in-degree over dst; record each edge's bucket rank
__global__ void k_hist(const int* __restrict__ dst) {
    int e = blockIdx.x * blockDim.x + threadIdx.x;
    if (e < NE) g_ppos[e] = atomicAdd(&g_deg[dst[e]], 1);
}

// 2) per-block exclusive scan of edge-counts; block sums; dinv = rsqrt(deg+1)
__global__ void k_scan1() {
    __shared__ int wsum[32];
    int i = blockIdx.x * 1024 + threadIdx.x;
    int lane = threadIdx.x & 31, wid = threadIdx.x >> 5;
    int v = (i < NN) ? g_deg[i] : 0;            // edges into i
    if (i < NN) g_dinv[i] = rsqrtf((float)(v + 1));
    int s = v;
    #pragma unroll
    for (int d = 1; d < 32; d <<= 1) {
        int t = __shfl_up_sync(0xffffffffu, s, d);
        if (lane >= d) s += t;
    }
    if (lane == 31) wsum[wid] = s;
    __syncthreads();
    if (wid == 0) {
        int ws = wsum[lane];
        #pragma unroll
        for (int d = 1; d < 32; d <<= 1) {
            int t = __shfl_up_sync(0xffffffffu, ws, d);
            if (lane >= d) ws += t;
        }
        wsum[lane] = ws;
    }
    __syncthreads();
    int ex = s - v + (wid ? wsum[wid - 1] : 0);
    if (i < NN) g_off[i] = ex;                  // block-local exclusive
    if (threadIdx.x == 1023) g_bsum[blockIdx.x] = ex + v;
}

// 3) per-block: add block offset (self-computed) and u0 = fp16(dinv.*x)
__global__ void k_scan23(const float* __restrict__ x) {
    __shared__ int sh_bex;
    if (threadIdx.x < 32) {
        int v = 0;
        for (int j = threadIdx.x; j < blockIdx.x; j += 32) v += g_bsum[j];
        #pragma unroll
        for (int d = 16; d; d >>= 1) v += __shfl_down_sync(0xffffffffu, v, d);
        if (threadIdx.x == 0) sh_bex = v;
    }
    __syncthreads();
    int i = blockIdx.x * 1024 + threadIdx.x;
    if (i < NN) g_off[i] += sh_bex;
    if (i == 0) g_off[NN] = NE;
    // fused prep for this block's node range (float2 in -> half2 out)
    int base = blockIdx.x * 1024 * 32;          // element-pair index
    const float2* x2 = (const float2*)x;
    __half2* u02 = (__half2*)g_u0;
    #pragma unroll 4
    for (int t = threadIdx.x; t < 1024 * 32; t += 1024) {
        int idx = base + t;
        if (idx < NN * 32) {
            float di = g_dinv[idx >> 5];
            float2 v = __ldg(&x2[idx]);
            float2 o; o.x = di * v.x; o.y = di * v.y;
            u02[idx] = __float22half2_rn(o);
        }
    }
}

// 4) scatter edge sources into CSR buckets by dst — NO atomics
__global__ void k_scatter(const int* __restrict__ src, const int* __restrict__ dst) {
    int e = blockIdx.x * blockDim.x + threadIdx.x;
    if (e < NE) {
        int d = dst[e];
        int p = __ldg(&g_off[d]) + g_ppos[e];
        g_csr_src[p] = src[e];
    }
}

// ---- hop: warp per node, fp16 row-sum gather, fp32 accumulation ----
// PASS 0: in = g_u0 (fp16), out = g_u1 (fp16), scale = dinv^2
// PASS 1: in = g_u1 (fp16), scale = dinv, then FUSED linear: out = h2 @ W^T + b
template <int PASS>
__global__ void k_hop(const float* __restrict__ W, const float* __restrict__ b,
                      float* __restrict__ out) {
    extern __shared__ ull sm[];      // PASS==1 only: Wp[2048] then bp[32]
    ull* Wp = sm;
    ull* bp = sm + D * 32;

    if (PASS == 1) {
        // Wp[k*32+c2] = (W[2c2][k], W[2c2+1][k]); bp[c2] = (b[2c2], b[2c2+1])
        for (int t = threadIdx.x; t < D * 32; t += blockDim.x) {
            int k = t >> 5, c2 = t & 31;
            float lo = __ldg(&W[(2 * c2) * D + k]);
            float hi = __ldg(&W[(2 * c2 + 1) * D + k]);
            ull u;
            asm("mov.b64 %0, {%1, %2};" : "=l"(u) : "f"(lo), "f"(hi));
            Wp[t] = u;
        }
        if (threadIdx.x < 32) {
            ull u;
            asm("mov.b64 %0, {%1, %2};" : "=l"(u)
                : "f"(__ldg(&b[2 * threadIdx.x])), "f"(__ldg(&b[2 * threadIdx.x + 1])));
            bp[threadIdx.x] = u;
        }
        __syncthreads();
    }

    const __half2* __restrict__ in2 =
        (PASS == 0) ? (const __half2*)g_u0 : (const __half2*)g_u1;

    int gw   = (blockIdx.x * blockDim.x + threadIdx.x) >> 5;
    int lane = threadIdx.x & 31;
    if (gw >= NN) return;            // never taken: NN*32 divides evenly into grid
    const int i = gw;
    float2 acc = __half22float2(__ldg(&in2[i * 32 + lane]));   // self term
    int beg = g_off[i], end = g_off[i + 1];
    for (int c = beg; c < end; c += 32) {
        int n = end - c; if (n > 32) n = 32;
        int myS = (c + lane < end) ? __ldg(&g_csr_src[c + lane]) : 0;
        int k = 0;
        for (; k + 8 <= n; k += 8) {
            int s0 = __shfl_sync(0xffffffffu, myS, k + 0);
            int s1 = __shfl_sync(0xffffffffu, myS, k + 1);
            int s2 = __shfl_sync(0xffffffffu, myS, k + 2);
            int s3 = __shfl_sync(0xffffffffu, myS, k + 3);
            int s4 = __shfl_sync(0xffffffffu, myS, k + 4);
            int s5 = __shfl_sync(0xffffffffu, myS, k + 5);
            int s6 = __shfl_sync(0xffffffffu, myS, k + 6);
            int s7 = __shfl_sync(0xffffffffu, myS, k + 7);
            __half2 v0 = __ldg(&in2[s0 * 32 + lane]);
            __half2 v1 = __ldg(&in2[s1 * 32 + lane]);
            __half2 v2 = __ldg(&in2[s2 * 32 + lane]);
            __half2 v3 = __ldg(&in2[s3 * 32 + lane]);
            __half2 v4 = __ldg(&in2[s4 * 32 + lane]);
            __half2 v5 = __ldg(&in2[s5 * 32 + lane]);
            __half2 v6 = __ldg(&in2[s6 * 32 + lane]);
            __half2 v7 = __ldg(&in2[s7 * 32 + lane]);
            float2 f0 = __half22float2(v0), f1 = __half22float2(v1);
            float2 f2 = __half22float2(v2), f3 = __half22float2(v3);
            float2 f4 = __half22float2(v4), f5 = __half22float2(v5);
            float2 f6 = __half22float2(v6), f7 = __half22float2(v7);
            acc.x += f0.x; acc.y += f0.y;
            acc.x += f1.x; acc.y += f1.y;
            acc.x += f2.x; acc.y += f2.y;
            acc.x += f3.x; acc.y += f3.y;
            acc.x += f4.x; acc.y += f4.y;
            acc.x += f5.x; acc.y += f5.y;
            acc.x += f6.x; acc.y += f6.y;
            acc.x += f7.x; acc.y += f7.y;
        }
        for (; k + 2 <= n; k += 2) {
            int s0 = __shfl_sync(0xffffffffu, myS, k + 0);
            int s1 = __shfl_sync(0xffffffffu, myS, k + 1);
            float2 f0 = __half22float2(__ldg(&in2[s0 * 32 + lane]));
            float2 f1 = __half22float2(__ldg(&in2[s1 * 32 + lane]));
            acc.x += f0.x; acc.y += f0.y;
            acc.x += f1.x; acc.y += f1.y;
        }
        if (k < n) {
            int s = __shfl_sync(0xffffffffu, myS, k);
            float2 f = __half22float2(__ldg(&in2[s * 32 + lane]));
            acc.x += f.x; acc.y += f.y;
        }
    }
    float di = g_dinv[i];
    if (PASS == 0) {
        float sc = di * di;
        acc.x *= sc; acc.y *= sc;
        ((__half2*)g_u1)[i * 32 + lane] = __float22half2_rn(acc);
    } else {
        // acc = h2[2*lane], h2[2*lane+1] (fp32, never stored)
        acc.x *= di; acc.y *= di;
        ull a = bp[lane];
        #pragma unroll
        for (int kk = 0; kk < 32; kk++) {
            float hx = __shfl_sync(0xffffffffu, acc.x, kk);  // h[2kk]
            float hy = __shfl_sync(0xffffffffu, acc.y, kk);  // h[2kk+1]
            ull w0 = Wp[(2 * kk) * 32 + lane];
            ull w1 = Wp[(2 * kk + 1) * 32 + lane];
            ull p0, p1;
            asm("mov.b64 %0, {%1, %1};" : "=l"(p0) : "f"(hx));
            asm("mov.b64 %0, {%1, %1};" : "=l"(p1) : "f"(hy));
            asm("fma.rn.f32x2 %0, %1, %2, %3;" : "=l"(a) : "l"(p0), "l"(w0), "l"(a));
            asm("fma.rn.f32x2 %0, %1, %2, %3;" : "=l"(a) : "l"(p1), "l"(w1), "l"(a));
        }
        ((ull*)out)[i * 32 + lane] = a;
    }
}

extern "C" void kernel_launch(void* const* d_in, const int* in_sizes, int n_in,
                              void* d_out, int out_size) {
    const float* x  = (const float*)d_in[0];                 // [NN, D]
    const int*   ei = (const int*)d_in[1];                   // [2, NE]
    const float* W  = (const float*)d_in[2];                 // [D, D]
    const float* b  = (const float*)d_in[3];                 // [D]
    const int* src = ei;
    const int* dst = ei + NE;
    float* out = (float*)d_out;

    void* deg_ptr = nullptr;
    cudaGetSymbolAddress(&deg_ptr, g_deg);
    cudaMemsetAsync(deg_ptr, 0, NN * sizeof(int));           // memset graph node

    const int SMEM_LIN = (D * 32 + 32) * sizeof(ull);        // 16640 B

    k_hist<<<(NE + 255) / 256, 256>>>(dst);
    k_scan1<<<NB, 1024>>>();
    k_scan23<<<NB, 1024>>>(x);
    k_scatter<<<(NE + 255) / 256, 256>>>(src, dst);
    k_hop<0><<<(NN * 32 + 255) / 256, 256>>>(nullptr, nullptr, nullptr);
    k_hop<1><<<(NN * 32 + 255) / 256, 256, SMEM_LIN>>>(W, b, out);
}

// round 9
// speedup vs baseline: 1.0076x; 1.0076x over previous
#include <cuda_runtime.h>
#include <cuda_fp16.h>

#define NN 100000
#define NE 1000000
#define D  64
#define NB 98   // ceil(NN/1024)

typedef unsigned long long ull;

// ---- device scratch (static, no allocation) ----
__device__ int     g_deg[NN];        // edge-count (self loop added in math)
__device__ float   g_dinv[NN];
__device__ int     g_off[NN + 1];
__device__ int     g_bsum[NB];
__device__ int     g_ppos[NE];       // per-edge rank within its dst bucket
__device__ int     g_csr_src[NE];
__device__ __half  g_u0[NN * D];     // fp16 intermediates
__device__ __half  g_u1[NN * D];

// 1) histogram of in-degree over dst; record each edge's bucket rank
__global__ void k_hist(const int* __restrict__ dst) {
    int e = blockIdx.x * blockDim.x + threadIdx.x;
    if (e < NE) g_ppos[e] = atomicAdd(&g_deg[dst[e]], 1);
}

// 2) per-block exclusive scan of edge-counts; block sums; dinv = rsqrt(deg+1)
__global__ void k_scan1() {
    __shared__ int wsum[32];
    int i = blockIdx.x * 1024 + threadIdx.x;
    int lane = threadIdx.x & 31, wid = threadIdx.x >> 5;
    int v = (i < NN) ? g_deg[i] : 0;            // edges into i
    if (i < NN) g_dinv[i] = rsqrtf((float)(v + 1));
    int s = v;
    #pragma unroll
    for (int d = 1; d < 32; d <<= 1) {
        int t = __shfl_up_sync(0xffffffffu, s, d);
        if (lane >= d) s += t;
    }
    if (lane == 31) wsum[wid] = s;
    __syncthreads();
    if (wid == 0) {
        int ws = wsum[lane];
        #pragma unroll
        for (int d = 1; d < 32; d <<= 1) {
            int t = __shfl_up_sync(0xffffffffu, ws, d);
            if (lane >= d) ws += t;
        }
        wsum[lane] = ws;
    }
    __syncthreads();
    int ex = s - v + (wid ? wsum[wid - 1] : 0);
    if (i < NN) g_off[i] = ex;                  // block-local exclusive
    if (threadIdx.x == 1023) g_bsum[blockIdx.x] = ex + v;
}

// 3) per-block: add block offset (self-computed) and u0 = fp16(dinv.*x)
__global__ void k_scan23(const float* __restrict__ x) {
    __shared__ int sh_bex;
    if (threadIdx.x < 32) {
        int v = 0;
        for (int j = threadIdx.x; j < blockIdx.x; j += 32) v += g_bsum[j];
        #pragma unroll
        for (int d = 16; d; d >>= 1) v += __shfl_down_sync(0xffffffffu, v, d);
        if (threadIdx.x == 0) sh_bex = v;
    }
    __syncthreads();
    int i = blockIdx.x * 1024 + threadIdx.x;
    if (i < NN) g_off[i] += sh_bex;
    if (i == 0) g_off[NN] = NE;
    // fused prep for this block's node range (float2 in -> half2 out)
    int base = blockIdx.x * 1024 * 32;          // element-pair index
    const float2* x2 = (const float2*)x;
    __half2* u02 = (__half2*)g_u0;
    #pragma unroll 4
    for (int t = threadIdx.x; t < 1024 * 32; t += 1024) {
        int idx = base + t;
        if (idx < NN * 32) {
            float di = g_dinv[idx >> 5];
            float2 v = __ldg(&x2[idx]);
            float2 o; o.x = di * v.x; o.y = di * v.y;
            u02[idx] = __float22half2_rn(o);
        }
    }
}

// 4) scatter edge sources into CSR buckets by dst — NO atomics
__global__ void k_scatter(const int* __restrict__ src, const int* __restrict__ dst) {
    int e = blockIdx.x * blockDim.x + threadIdx.x;
    if (e < NE) {
        int d = dst[e];
        int p = __ldg(&g_off[d]) + g_ppos[e];
        g_csr_src[p] = src[e];
    }
}

// ---- shared gather body: warp-per-node fp16 row sum, fp32 accumulation ----
__device__ __forceinline__ float2 gather_row(const __half2* __restrict__ in2,
                                             int i, int lane) {
    float2 acc = __half22float2(__ldg(&in2[i * 32 + lane]));   // self term
    int beg = g_off[i], end = g_off[i + 1];
    for (int c = beg; c < end; c += 32) {
        int n = end - c; if (n > 32) n = 32;
        int myS = (c + lane < end) ? __ldg(&g_csr_src[c + lane]) : 0;
        int k = 0;
        for (; k + 8 <= n; k += 8) {
            int s0 = __shfl_sync(0xffffffffu, myS, k + 0);
            int s1 = __shfl_sync(0xffffffffu, myS, k + 1);
            int s2 = __shfl_sync(0xffffffffu, myS, k + 2);
            int s3 = __shfl_sync(0xffffffffu, myS, k + 3);
            int s4 = __shfl_sync(0xffffffffu, myS, k + 4);
            int s5 = __shfl_sync(0xffffffffu, myS, k + 5);
            int s6 = __shfl_sync(0xffffffffu, myS, k + 6);
            int s7 = __shfl_sync(0xffffffffu, myS, k + 7);
            __half2 v0 = __ldg(&in2[s0 * 32 + lane]);
            __half2 v1 = __ldg(&in2[s1 * 32 + lane]);
            __half2 v2 = __ldg(&in2[s2 * 32 + lane]);
            __half2 v3 = __ldg(&in2[s3 * 32 + lane]);
            __half2 v4 = __ldg(&in2[s4 * 32 + lane]);
            __half2 v5 = __ldg(&in2[s5 * 32 + lane]);
            __half2 v6 = __ldg(&in2[s6 * 32 + lane]);
            __half2 v7 = __ldg(&in2[s7 * 32 + lane]);
            float2 f0 = __half22float2(v0), f1 = __half22float2(v1);
            float2 f2 = __half22float2(v2), f3 = __half22float2(v3);
            float2 f4 = __half22float2(v4), f5 = __half22float2(v5);
            float2 f6 = __half22float2(v6), f7 = __half22float2(v7);
            acc.x += f0.x; acc.y += f0.y;
            acc.x += f1.x; acc.y += f1.y;
            acc.x += f2.x; acc.y += f2.y;
            acc.x += f3.x; acc.y += f3.y;
            acc.x += f4.x; acc.y += f4.y;
            acc.x += f5.x; acc.y += f5.y;
            acc.x += f6.x; acc.y += f6.y;
            acc.x += f7.x; acc.y += f7.y;
        }
        for (; k + 2 <= n; k += 2) {
            int s0 = __shfl_sync(0xffffffffu, myS, k + 0);
            int s1 = __shfl_sync(0xffffffffu, myS, k + 1);
            float2 f0 = __half22float2(__ldg(&in2[s0 * 32 + lane]));
            float2 f1 = __half22float2(__ldg(&in2[s1 * 32 + lane]));
            acc.x += f0.x; acc.y += f0.y;
            acc.x += f1.x; acc.y += f1.y;
        }
        if (k < n) {
            int s = __shfl_sync(0xffffffffu, myS, k);
            float2 f = __half22float2(__ldg(&in2[s * 32 + lane]));
            acc.x += f.x; acc.y += f.y;
        }
    }
    return acc;
}

// 5) hop 0: u1 = fp16( dinv^2 * (u0[i] + sum u0[s]) )   — identical to R7
__global__ void k_hop0() {
    int gw   = (blockIdx.x * blockDim.x + threadIdx.x) >> 5;
    int lane = threadIdx.x & 31;
    if (gw >= NN) return;
    float2 acc = gather_row((const __half2*)g_u0, gw, lane);
    float di = g_dinv[gw];
    float sc = di * di;
    acc.x *= sc; acc.y *= sc;
    ((__half2*)g_u1)[gw * 32 + lane] = __float22half2_rn(acc);
}

// 6) hop 1 + fused linear: out = (dinv * (u1[i] + sum u1[s])) @ W^T + b
__global__ void __launch_bounds__(256, 6)
k_hop1_fused(const float* __restrict__ W, const float* __restrict__ b,
             float* __restrict__ out) {
    __shared__ ull Wp[D * 32];   // Wp[k*32+c2] = (W[2c2][k], W[2c2+1][k])
    __shared__ ull bp[32];

    for (int t = threadIdx.x; t < D * 32; t += 256) {
        int k = t >> 5, c2 = t & 31;
        float lo = __ldg(&W[(2 * c2) * D + k]);
        float hi = __ldg(&W[(2 * c2 + 1) * D + k]);
        ull u;
        asm("mov.b64 %0, {%1, %2};" : "=l"(u) : "f"(lo), "f"(hi));
        Wp[t] = u;
    }
    if (threadIdx.x < 32) {
        ull u;
        asm("mov.b64 %0, {%1, %2};" : "=l"(u)
            : "f"(__ldg(&b[2 * threadIdx.x])), "f"(__ldg(&b[2 * threadIdx.x + 1])));
        bp[threadIdx.x] = u;
    }
    __syncthreads();

    int gw   = (blockIdx.x * blockDim.x + threadIdx.x) >> 5;
    int lane = threadIdx.x & 31;
    if (gw >= NN) return;
    float2 acc = gather_row((const __half2*)g_u1, gw, lane);
    float di = g_dinv[gw];
    acc.x *= di; acc.y *= di;                // h2[2*lane], h2[2*lane+1] in regs

    ull a = bp[lane];
    #pragma unroll 4
    for (int kk = 0; kk < 32; kk++) {
        float hx = __shfl_sync(0xffffffffu, acc.x, kk);  // h[2kk]
        float hy = __shfl_sync(0xffffffffu, acc.y, kk);  // h[2kk+1]
        ull w0 = Wp[(2 * kk) * 32 + lane];
        ull w1 = Wp[(2 * kk + 1) * 32 + lane];
        ull p0, p1;
        asm("mov.b64 %0, {%1, %1};" : "=l"(p0) : "f"(hx));
        asm("mov.b64 %0, {%1, %1};" : "=l"(p1) : "f"(hy));
        asm("fma.rn.f32x2 %0, %1, %2, %3;" : "=l"(a) : "l"(p0), "l"(w0), "l"(a));
        asm("fma.rn.f32x2 %0, %1, %2, %3;" : "=l"(a) : "l"(p1), "l"(w1), "l"(a));
    }
    ((ull*)out)[gw * 32 + lane] = a;
}

extern "C" void kernel_launch(void* const* d_in, const int* in_sizes, int n_in,
                              void* d_out, int out_size) {
    const float* x  = (const float*)d_in[0];                 // [NN, D]
    const int*   ei = (const int*)d_in[1];                   // [2, NE]
    const float* W  = (const float*)d_in[2];                 // [D, D]
    const float* b  = (const float*)d_in[3];                 // [D]
    const int* src = ei;
    const int* dst = ei + NE;
    float* out = (float*)d_out;

    void* deg_ptr = nullptr;
    cudaGetSymbolAddress(&deg_ptr, g_deg);
    cudaMemsetAsync(deg_ptr, 0, NN * sizeof(int));           // memset graph node

    k_hist<<<(NE + 255) / 256, 256>>>(dst);
    k_scan1<<<NB, 1024>>>();
    k_scan23<<<NB, 1024>>>(x);
    k_scatter<<<(NE + 255) / 256, 256>>>(src, dst);
    k_hop0<<<(NN * 32 + 255) / 256, 256>>>();
    k_hop1_fused<<<(NN * 32 + 255) / 256, 256>>>(W, b, out);
}

// round 10
// speedup vs baseline: 2.3960x; 2.3780x over previous
#include <cuda_runtime.h>
#include <cuda_fp16.h>

#define NN 100000
#define NE 1000000
#define D  64
#define NB 98   // ceil(NN/1024)

// ---- device scratch (static, no allocation; zero-initialized at load) ----
__device__ int     g_deg[NN];        // edge-count; re-zeroed each run by k_scan23
__device__ float   g_dinv[NN];
__device__ int     g_off[NN + 1];
__device__ int     g_bsum[NB];
__device__ int     g_ppos[NE];       // per-edge rank within its dst bucket
__device__ int     g_csr_src[NE];
__device__ __half  g_u0[NN * D];     // fp16 intermediates
__device__ __half  g_u1[NN * D];
__device__ __half  g_h2[NN * D];

// 1) histogram of in-degree over dst; record each edge's bucket rank
__global__ void k_hist(const int* __restrict__ dst) {
    int e = blockIdx.x * blockDim.x + threadIdx.x;
    if (e < NE) g_ppos[e] = atomicAdd(&g_deg[dst[e]], 1);
}

// 2) per-block exclusive scan of edge-counts; block sums; dinv = rsqrt(deg+1)
__global__ void k_scan1() {
    __shared__ int wsum[32];
    int i = blockIdx.x * 1024 + threadIdx.x;
    int lane = threadIdx.x & 31, wid = threadIdx.x >> 5;
    int v = (i < NN) ? g_deg[i] : 0;            // edges into i
    if (i < NN) g_dinv[i] = rsqrtf((float)(v + 1));
    int s = v;
    #pragma unroll
    for (int d = 1; d < 32; d <<= 1) {
        int t = __shfl_up_sync(0xffffffffu, s, d);
        if (lane >= d) s += t;
    }
    if (lane == 31) wsum[wid] = s;
    __syncthreads();
    if (wid == 0) {
        int ws = wsum[lane];
        #pragma unroll
        for (int d = 1; d < 32; d <<= 1) {
            int t = __shfl_up_sync(0xffffffffu, ws, d);
            if (lane >= d) ws += t;
        }
        wsum[lane] = ws;
    }
    __syncthreads();
    int ex = s - v + (wid ? wsum[wid - 1] : 0);
    if (i < NN) g_off[i] = ex;                  // block-local exclusive
    if (threadIdx.x == 1023) g_bsum[blockIdx.x] = ex + v;
}

// 3) per-block: add block offset (self-computed), re-zero g_deg for next run,
//    and u0 = fp16(dinv.*x)
__global__ void k_scan23(const float* __restrict__ x) {
    __shared__ int sh_bex;
    if (threadIdx.x < 32) {
        int v = 0;
        for (int j = threadIdx.x; j < blockIdx.x; j += 32) v += g_bsum[j];
        #pragma unroll
        for (int d = 16; d; d >>= 1) v += __shfl_down_sync(0xffffffffu, v, d);
        if (threadIdx.x == 0) sh_bex = v;
    }
    __syncthreads();
    int i = blockIdx.x * 1024 + threadIdx.x;
    if (i < NN) {
        g_off[i] += sh_bex;
        g_deg[i] = 0;                 // restore for next graph replay
    }
    if (i == 0) g_off[NN] = NE;
    // fused prep for this block's node range (float2 in -> half2 out)
    int base = blockIdx.x * 1024 * 32;          // element-pair index
    const float2* x2 = (const float2*)x;
    __half2* u02 = (__half2*)g_u0;
    #pragma unroll 4
    for (int t = threadIdx.x; t < 1024 * 32; t += 1024) {
        int idx = base + t;
        if (idx < NN * 32) {
            float di = g_dinv[idx >> 5];
            float2 v = __ldg(&x2[idx]);
            float2 o; o.x = di * v.x; o.y = di * v.y;
            u02[idx] = __float22half2_rn(o);
        }
    }
}

// 4) scatter edge sources into CSR buckets by dst — NO atomics
__global__ void k_scatter(const int* __restrict__ src, const int* __restrict__ dst) {
    int e = blockIdx.x * blockDim.x + threadIdx.x;
    if (e < NE) {
        int d = dst[e];
        int p = __ldg(&g_off[d]) + g_ppos[e];
        g_csr_src[p] = src[e];
    }
}

// ---- hop: warp per node, fp16 row-sum gather, fp32 accumulation ----
// PASS 0: in = g_u0 (fp16), out = g_u1 (fp16), scale = dinv^2
// PASS 1: in = g_u1 (fp16), out = g_h2 (fp16), scale = dinv
template <int PASS>
__global__ void k_hop() {
    const __half2* __restrict__ in2 =
        (PASS == 0) ? (const __half2*)g_u0 : (const __half2*)g_u1;

    int gw   = (blockIdx.x * blockDim.x + threadIdx.x) >> 5;
    int lane = threadIdx.x & 31;
    if (gw >= NN) return;
    const int i = gw;
    float2 acc = __half22float2(__ldg(&in2[i * 32 + lane]));   // self term
    int beg = g_off[i], end = g_off[i + 1];
    for (int c = beg; c < end; c += 32) {
        int n = end - c; if (n > 32) n = 32;
        int myS = (c + lane < end) ? __ldg(&g_csr_src[c + lane]) : 0;
        int k = 0;
        for (; k + 8 <= n; k += 8) {
            int s0 = __shfl_sync(0xffffffffu, myS, k + 0);
            int s1 = __shfl_sync(0xffffffffu, myS, k + 1);
            int s2 = __shfl_sync(0xffffffffu, myS, k + 2);
            int s3 = __shfl_sync(0xffffffffu, myS, k + 3);
            int s4 = __shfl_sync(0xffffffffu, myS, k + 4);
            int s5 = __shfl_sync(0xffffffffu, myS, k + 5);
            int s6 = __shfl_sync(0xffffffffu, myS, k + 6);
            int s7 = __shfl_sync(0xffffffffu, myS, k + 7);
            __half2 v0 = __ldg(&in2[s0 * 32 + lane]);
            __half2 v1 = __ldg(&in2[s1 * 32 + lane]);
            __half2 v2 = __ldg(&in2[s2 * 32 + lane]);
            __half2 v3 = __ldg(&in2[s3 * 32 + lane]);
            __half2 v4 = __ldg(&in2[s4 * 32 + lane]);
            __half2 v5 = __ldg(&in2[s5 * 32 + lane]);
            __half2 v6 = __ldg(&in2[s6 * 32 + lane]);
            __half2 v7 = __ldg(&in2[s7 * 32 + lane]);
            float2 f0 = __half22float2(v0), f1 = __half22float2(v1);
            float2 f2 = __half22float2(v2), f3 = __half22float2(v3);
            float2 f4 = __half22float2(v4), f5 = __half22float2(v5);
            float2 f6 = __half22float2(v6), f7 = __half22float2(v7);
            acc.x += f0.x; acc.y += f0.y;
            acc.x += f1.x; acc.y += f1.y;
            acc.x += f2.x; acc.y += f2.y;
            acc.x += f3.x; acc.y += f3.y;
            acc.x += f4.x; acc.y += f4.y;
            acc.x += f5.x; acc.y += f5.y;
            acc.x += f6.x; acc.y += f6.y;
            acc.x += f7.x; acc.y += f7.y;
        }
        for (; k + 2 <= n; k += 2) {
            int s0 = __shfl_sync(0xffffffffu, myS, k + 0);
            int s1 = __shfl_sync(0xffffffffu, myS, k + 1);
            float2 f0 = __half22float2(__ldg(&in2[s0 * 32 + lane]));
            float2 f1 = __half22float2(__ldg(&in2[s1 * 32 + lane]));
            acc.x += f0.x; acc.y += f0.y;
            acc.x += f1.x; acc.y += f1.y;
        }
        if (k < n) {
            int s = __shfl_sync(0xffffffffu, myS, k);
            float2 f = __half22float2(__ldg(&in2[s * 32 + lane]));
            acc.x += f.x; acc.y += f.y;
        }
    }
    float di = g_dinv[i];
    if (PASS == 0) {
        float sc = di * di;
        acc.x *= sc; acc.y *= sc;
        ((__half2*)g_u1)[i * 32 + lane] = __float22half2_rn(acc);
    } else {
        acc.x *= di; acc.y *= di;
        ((__half2*)g_h2)[i * 32 + lane] = __float22half2_rn(acc);
    }
}

// 5) out = g_h2 @ W^T + b  (packed fma.rn.f32x2: 2 cols x 4 rows per thread)
__global__ void k_lin(const float* __restrict__ W, const float* __restrict__ b,
                      float* __restrict__ out) {
    __shared__ unsigned long long Wp[D * 32];   // Wp[k*32+c2] = (W[2c2][k], W[2c2+1][k])
    __shared__ float hs[32 * D];                // 32 staged rows
    __shared__ unsigned long long bp[32];

    for (int t = threadIdx.x; t < D * 32; t += 256) {
        int k = t >> 5, c2 = t & 31;
        float lo = W[(2 * c2) * D + k];
        float hi = W[(2 * c2 + 1) * D + k];
        unsigned long long u;
        asm("mov.b64 %0, {%1, %2};" : "=l"(u) : "f"(lo), "f"(hi));
        Wp[t] = u;
    }
    if (threadIdx.x < 32) {
        unsigned long long u;
        asm("mov.b64 %0, {%1, %2};" : "=l"(u)
            : "f"(b[2 * threadIdx.x]), "f"(b[2 * threadIdx.x + 1]));
        bp[threadIdx.x] = u;
    }
    __syncthreads();

    int wid = threadIdx.x >> 5, lane = threadIdx.x & 31;

    for (int r0 = blockIdx.x * 32; r0 < NN; r0 += gridDim.x * 32) {
        const __half2* src = (const __half2*)g_h2 + r0 * 32;
        #pragma unroll
        for (int t = threadIdx.x; t < 1024; t += 256)
            ((float2*)hs)[t] = __half22float2(__ldg(&src[t]));
        __syncthreads();

        unsigned long long a0 = bp[lane], a1 = a0, a2 = a0, a3 = a0;
        const float* h0 = &hs[(wid * 4 + 0) * D];
        const float* h1 = &hs[(wid * 4 + 1) * D];
        const float* h2 = &hs[(wid * 4 + 2) * D];
        const float* h3 = &hs[(wid * 4 + 3) * D];
        #pragma unroll
        for (int k = 0; k < D; k++) {
            unsigned long long wv = Wp[k * 32 + lane];
            float v0 = h0[k], v1 = h1[k], v2 = h2[k], v3 = h3[k];
            unsigned long long p0, p1, p2, p3;
            asm("mov.b64 %0, {%1, %1};" : "=l"(p0) : "f"(v0));
            asm("mov.b64 %0, {%1, %1};" : "=l"(p1) : "f"(v1));
            asm("mov.b64 %0, {%1, %1};" : "=l"(p2) : "f"(v2));
            asm("mov.b64 %0, {%1, %1};" : "=l"(p3) : "f"(v3));
            asm("fma.rn.f32x2 %0, %1, %2, %3;" : "=l"(a0) : "l"(p0), "l"(wv), "l"(a0));
            asm("fma.rn.f32x2 %0, %1, %2, %3;" : "=l"(a1) : "l"(p1), "l"(wv), "l"(a1));
            asm("fma.rn.f32x2 %0, %1, %2, %3;" : "=l"(a2) : "l"(p2), "l"(wv), "l"(a2));
            asm("fma.rn.f32x2 %0, %1, %2, %3;" : "=l"(a3) : "l"(p3), "l"(wv), "l"(a3));
        }
        int r = r0 + wid * 4;
        unsigned long long* o = (unsigned long long*)out;
        o[(r + 0) * 32 + lane] = a0;
        o[(r + 1) * 32 + lane] = a1;
        o[(r + 2) * 32 + lane] = a2;
        o[(r + 3) * 32 + lane] = a3;
        __syncthreads();
    }
}

extern "C" void kernel_launch(void* const* d_in, const int* in_sizes, int n_in,
                              void* d_out, int out_size) {
    const float* x  = (const float*)d_in[0];                 // [NN, D]
    const int*   ei = (const int*)d_in[1];                   // [2, NE]
    const float* W  = (const float*)d_in[2];                 // [D, D]
    const float* b  = (const float*)d_in[3];                 // [D]
    const int* src = ei;
    const int* dst = ei + NE;
    float* out = (float*)d_out;

    // g_deg starts zeroed (static init) and is re-zeroed by k_scan23 each run.
    k_hist<<<(NE + 255) / 256, 256>>>(dst);
    k_scan1<<<NB, 1024>>>();
    k_scan23<<<NB, 1024>>>(x);
    k_scatter<<<(NE + 255) / 256, 256>>>(src, dst);
    k_hop<0><<<(NN * 32 + 255) / 256, 256>>>();
    k_hop<1><<<(NN * 32 + 255) / 256, 256>>>();
    k_lin<<<1184, 256>>>(W, b, out);
}